// round 1
// baseline (speedup 1.0000x reference)
#include <cuda_runtime.h>

#define VOCABN 32000
#define EMBEDN 256
#define H1N    512
#define KVN    128
#define BN_    32
#define SN     512
#define TN     256
#define MROWS  (BN_*TN)   // 8192

// ---------------- scratch (static device globals; no allocation) ----------------
__device__ float g_gates1[MROWS * 4 * H1N];   // 8192 x 2048
__device__ float g_h1    [MROWS * H1N];       // 8192 x 512
__device__ float g_gates2[MROWS * 4 * KVN];   // 8192 x 512
__device__ float g_h2    [MROWS * KVN];       // 8192 x 128
__device__ float g_energy[MROWS * SN];        // 8192 x 512 (attn in-place)
__device__ float g_valueT[BN_ * KVN * SN];    // 32 x 128 x 512
__device__ float g_outctx[MROWS * EMBEDN];    // 8192 x 256

// ---------------- helpers ----------------
__device__ __forceinline__ unsigned f2tf32(float x) {
    unsigned r;
    asm("cvt.rna.tf32.f32 %0, %1;" : "=r"(r) : "f"(x));
    return r;
}
__device__ __forceinline__ float sigf(float x) { return 1.f / (1.f + expf(-x)); }

// ---------------- generic tiled TN GEMM: C[m,n] = sum_k A[m,k]*B[n,k] ----------------
// BM=128, BN=128, BK=32; 256 threads = 8 warps in 2(m) x 4(n); warp tile 64x32
// MODE 0: plain store (batched via z strides)
// MODE 1: A rows gathered from embedding table via token ids
// MODE 2: energy epilogue (mask cols >= enc_len[z] to -1e9)
// MODE 3: logits epilogue (add bias[m]; store out[b][m][t] with n = b*T + t)
#define GBM 128
#define GBN 128
#define GBK 32
#define GPAD 4

template <int MODE>
__global__ void __launch_bounds__(256)
gemm_tn(const float* __restrict__ A, const float* __restrict__ Bmat,
        float* __restrict__ C,
        int K, int lda, int ldb, int ldc,
        long sA, long sB, long sC,
        const int* __restrict__ ytok,
        const int* __restrict__ enc_len,
        const float* __restrict__ bias)
{
    __shared__ unsigned As[GBM][GBK + GPAD];
    __shared__ unsigned Bs[GBN][GBK + GPAD];

    const int tid  = threadIdx.x;
    const int warp = tid >> 5, lane = tid & 31;
    const int wm = warp >> 2, wn = warp & 3;
    const int g  = lane >> 2, tq = lane & 3;
    const int bm0 = blockIdx.y * GBM;
    const int bn0 = blockIdx.x * GBN;
    const int z   = blockIdx.z;

    const float* Ab = A    + (long)z * sA;
    const float* Bb = Bmat + (long)z * sB;

    float acc[4][4][4];
#pragma unroll
    for (int i = 0; i < 4; i++)
#pragma unroll
        for (int j = 0; j < 4; j++)
#pragma unroll
            for (int q = 0; q < 4; q++) acc[i][j][q] = 0.f;

    for (int k0 = 0; k0 < K; k0 += GBK) {
#pragma unroll
        for (int i = 0; i < 4; i++) {
            int f  = tid + i * 256;       // 1024 float4 slots
            int r  = f >> 3;              // row 0..127
            int c4 = (f & 7) << 2;        // col 0,4,...,28
            const float* srca;
            if (MODE == 1) {
                int m   = bm0 + r;
                int tok = ((m & (TN - 1)) == 0) ? 0 : ytok[m - 1];
                srca = Ab + (long)tok * lda + k0 + c4;
            } else {
                srca = Ab + (long)(bm0 + r) * lda + k0 + c4;
            }
            float4 va = *reinterpret_cast<const float4*>(srca);
            As[r][c4 + 0] = f2tf32(va.x);
            As[r][c4 + 1] = f2tf32(va.y);
            As[r][c4 + 2] = f2tf32(va.z);
            As[r][c4 + 3] = f2tf32(va.w);

            const float* srcb = Bb + (long)(bn0 + r) * ldb + k0 + c4;
            float4 vb = *reinterpret_cast<const float4*>(srcb);
            Bs[r][c4 + 0] = f2tf32(vb.x);
            Bs[r][c4 + 1] = f2tf32(vb.y);
            Bs[r][c4 + 2] = f2tf32(vb.z);
            Bs[r][c4 + 3] = f2tf32(vb.w);
        }
        __syncthreads();

#pragma unroll
        for (int kk = 0; kk < GBK; kk += 8) {
            unsigned af[4][4], bf[4][2];
#pragma unroll
            for (int mi = 0; mi < 4; mi++) {
                int r0 = wm * 64 + mi * 16 + g;
                af[mi][0] = As[r0    ][kk + tq];
                af[mi][1] = As[r0 + 8][kk + tq];
                af[mi][2] = As[r0    ][kk + tq + 4];
                af[mi][3] = As[r0 + 8][kk + tq + 4];
            }
#pragma unroll
            for (int ni = 0; ni < 4; ni++) {
                int c0 = wn * 32 + ni * 8 + g;
                bf[ni][0] = Bs[c0][kk + tq];
                bf[ni][1] = Bs[c0][kk + tq + 4];
            }
#pragma unroll
            for (int mi = 0; mi < 4; mi++)
#pragma unroll
                for (int ni = 0; ni < 4; ni++)
                    asm volatile(
                        "mma.sync.aligned.m16n8k8.row.col.f32.tf32.tf32.f32 "
                        "{%0,%1,%2,%3}, {%4,%5,%6,%7}, {%8,%9}, {%0,%1,%2,%3};\n"
                        : "+f"(acc[mi][ni][0]), "+f"(acc[mi][ni][1]),
                          "+f"(acc[mi][ni][2]), "+f"(acc[mi][ni][3])
                        : "r"(af[mi][0]), "r"(af[mi][1]),
                          "r"(af[mi][2]), "r"(af[mi][3]),
                          "r"(bf[ni][0]), "r"(bf[ni][1]));
        }
        __syncthreads();
    }

    // epilogue
#pragma unroll
    for (int mi = 0; mi < 4; mi++) {
#pragma unroll
        for (int ni = 0; ni < 4; ni++) {
            int row = bm0 + wm * 64 + mi * 16 + g;
            int col = bn0 + wn * 32 + ni * 8 + 2 * tq;
#pragma unroll
            for (int rr = 0; rr < 2; rr++) {
                int r = row + rr * 8;
                float v0 = acc[mi][ni][rr * 2 + 0];
                float v1 = acc[mi][ni][rr * 2 + 1];
                if (MODE == 2) {
                    int len = enc_len[z];
                    if (col     >= len) v0 = -1e9f;
                    if (col + 1 >= len) v1 = -1e9f;
                }
                if (MODE == 3) {
                    float bb = bias[r];
                    v0 += bb; v1 += bb;
                    int bidx = col >> 8;     // T = 256
                    int t    = col & 255;
                    float2 vv = make_float2(v0, v1);
                    *reinterpret_cast<float2*>(
                        C + (long)bidx * VOCABN * TN + (long)r * TN + t) = vv;
                } else {
                    float2 vv = make_float2(v0, v1);
                    *reinterpret_cast<float2*>(
                        C + (long)z * sC + (long)r * ldc + col) = vv;
                }
            }
        }
    }
}

// ---------------- elementwise LSTM-cell activation (zero state) ----------------
__global__ void act_lstm(const float* __restrict__ gates,
                         const float* __restrict__ b_ih,
                         const float* __restrict__ b_hh,
                         float* __restrict__ h,
                         float* __restrict__ hcopy, int H, int ldcopy, long total)
{
    long idx = (long)blockIdx.x * blockDim.x + threadIdx.x;
    if (idx >= total) return;
    int  j = (int)(idx & (H - 1));
    long m = idx / H;
    const float* gr = gates + m * 4 * H;
    float iv = gr[j]         + b_ih[j]         + b_hh[j];
    float gv = gr[2 * H + j] + b_ih[2 * H + j] + b_hh[2 * H + j];
    float ov = gr[3 * H + j] + b_ih[3 * H + j] + b_hh[3 * H + j];
    float c  = sigf(iv) * tanhf(gv);
    float hv = sigf(ov) * tanhf(c);
    h[m * H + j] = hv;
    if (hcopy) hcopy[m * ldcopy + j] = hv;
}

// ---------------- per-row softmax over S=512, in place ----------------
__global__ void softmax_rows(float* __restrict__ e)
{
    const int row = blockIdx.x;
    float* p = e + (long)row * SN;
    __shared__ float red[128];
    int tid = threadIdx.x;
    float v0 = p[tid], v1 = p[tid + 128], v2 = p[tid + 256], v3 = p[tid + 384];
    float mx = fmaxf(fmaxf(v0, v1), fmaxf(v2, v3));
    red[tid] = mx; __syncthreads();
    for (int st = 64; st > 0; st >>= 1) {
        if (tid < st) red[tid] = fmaxf(red[tid], red[tid + st]);
        __syncthreads();
    }
    mx = red[0]; __syncthreads();
    v0 = expf(v0 - mx); v1 = expf(v1 - mx); v2 = expf(v2 - mx); v3 = expf(v3 - mx);
    float s = v0 + v1 + v2 + v3;
    red[tid] = s; __syncthreads();
    for (int st = 64; st > 0; st >>= 1) {
        if (tid < st) red[tid] += red[tid + st];
        __syncthreads();
    }
    float inv = 1.f / red[0];
    p[tid] = v0 * inv; p[tid + 128] = v1 * inv;
    p[tid + 256] = v2 * inv; p[tid + 384] = v3 * inv;
}

// ---------------- value transpose: (B,S,KV) -> (B,KV,S) ----------------
__global__ void transpose_v(const float* __restrict__ v, float* __restrict__ vt)
{
    __shared__ float tile[32][33];
    int b  = blockIdx.z;
    int s0 = blockIdx.y * 32, v0 = blockIdx.x * 32;
    int x = threadIdx.x, y = threadIdx.y;   // 32 x 8
#pragma unroll
    for (int i = 0; i < 32; i += 8)
        tile[y + i][x] = v[((long)b * SN + s0 + y + i) * KVN + v0 + x];
    __syncthreads();
#pragma unroll
    for (int i = 0; i < 32; i += 8)
        vt[((long)b * KVN + v0 + y + i) * SN + s0 + x] = tile[x][y + i];
}

// ---------------- launch ----------------
extern "C" void kernel_launch(void* const* d_in, const int* in_sizes, int n_in,
                              void* d_out, int out_size)
{
    const float* key   = (const float*)d_in[0];
    const float* value = (const float*)d_in[1];
    const int*   elen  = (const int*)  d_in[2];
    const int*   y     = (const int*)  d_in[3];
    const float* E     = (const float*)d_in[4];
    const float* W1    = (const float*)d_in[5];
    const float* bi1   = (const float*)d_in[6];
    const float* bh1   = (const float*)d_in[7];
    const float* W2    = (const float*)d_in[8];
    const float* bi2   = (const float*)d_in[9];
    const float* bh2   = (const float*)d_in[10];
    const float* bout  = (const float*)d_in[11];
    float*       out   = (float*)d_out;

    float *gates1, *h1p, *gates2, *h2p, *energy, *valueT, *outctx;
    cudaGetSymbolAddress((void**)&gates1, g_gates1);
    cudaGetSymbolAddress((void**)&h1p,    g_h1);
    cudaGetSymbolAddress((void**)&gates2, g_gates2);
    cudaGetSymbolAddress((void**)&h2p,    g_h2);
    cudaGetSymbolAddress((void**)&energy, g_energy);
    cudaGetSymbolAddress((void**)&valueT, g_valueT);
    cudaGetSymbolAddress((void**)&outctx, g_outctx);

    // 1) gates1 = embed(tokens) @ W1^T     (M=8192, N=2048, K=256)
    gemm_tn<1><<<dim3(2048 / GBN, MROWS / GBM, 1), 256>>>(
        E, W1, gates1, EMBEDN, EMBEDN, EMBEDN, 4 * H1N,
        0, 0, 0, y, nullptr, nullptr);

    // 2) h1 = lstm_act(gates1)
    {
        long total = (long)MROWS * H1N;
        act_lstm<<<(unsigned)((total + 255) / 256), 256>>>(
            gates1, bi1, bh1, h1p, nullptr, H1N, 0, total);
    }

    // 3) gates2 = h1 @ W2^T                (M=8192, N=512, K=512)
    gemm_tn<0><<<dim3(512 / GBN, MROWS / GBM, 1), 256>>>(
        h1p, W2, gates2, H1N, H1N, H1N, 4 * KVN,
        0, 0, 0, nullptr, nullptr, nullptr);

    // 4) h2 = lstm_act(gates2); also copy into out_ctx[:, 0:128]
    {
        long total = (long)MROWS * KVN;
        act_lstm<<<(unsigned)((total + 255) / 256), 256>>>(
            gates2, bi2, bh2, h2p, outctx, KVN, EMBEDN, total);
    }

    // 5) valueT[b][v][s] = value[b][s][v]
    transpose_v<<<dim3(KVN / 32, SN / 32, BN_), dim3(32, 8)>>>(value, valueT);

    // 6) energy[b,t,s] = h2[b,t,:] . key[b,s,:], masked   (per b: M=256, N=512, K=128)
    gemm_tn<2><<<dim3(SN / GBN, TN / GBM, BN_), 256>>>(
        h2p, key, energy, KVN, KVN, KVN, SN,
        (long)TN * KVN, (long)SN * KVN, (long)TN * SN,
        nullptr, elen, nullptr);

    // 7) softmax over s
    softmax_rows<<<MROWS, 128>>>(energy);

    // 8) context = attn @ value  -> out_ctx[:, 128:256]   (per b: M=256, N=128, K=512)
    gemm_tn<0><<<dim3(KVN / GBN, TN / GBM, BN_), 256>>>(
        energy, valueT, outctx + KVN, SN, SN, SN, EMBEDN,
        (long)TN * SN, (long)KVN * SN, (long)TN * EMBEDN,
        nullptr, nullptr, nullptr);

    // 9) logits = E @ out_ctx^T + b_out, stored as out[b][v][t]
    //    (M=32000, N=8192, K=256)
    gemm_tn<3><<<dim3(MROWS / GBN, VOCABN / GBM, 1), 256>>>(
        E, outctx, out, EMBEDN, EMBEDN, EMBEDN, 0,
        0, 0, 0, nullptr, nullptr, bout);

    (void)in_sizes; (void)n_in; (void)out_size;
}